// round 13
// baseline (speedup 1.0000x reference)
#include <cuda_runtime.h>
#include <cuda_fp16.h>
#include <cstdint>
#include <cstddef>

// Problem constants
#define Bb 8
#define Ss 1024
#define Hh 256
#define LL 7
#define BSR (Bb*Ss)        // 8192 rows
#define H7 (7*Hh)          // 1792
#define H3 (3*Hh)          // 768
#define NCH 64
#define SCH (Ss/NCH)       // 16

// ---------------- scratch (device globals; no allocations allowed) ----------
__device__ float d_hbuf0[BSR*Hh];
__device__ float d_hbuf1[BSR*Hh];
__device__ float d_cbuf0[BSR*Hh];
__device__ float d_cbuf1[BSR*Hh];
__device__ float d_proj[(size_t)BSR*H7];
__device__ float d_zbuf[(size_t)BSR*H7];
__device__ float d_ph[BSR*Hh];
__device__ float d_pi[Bb*H3];
__device__ float d_pa[Bb*2*Hh];
__device__ float d_igb[Bb*Hh];
__device__ float d_ogb[Bb*Hh];
__device__ float d_gh[Bb*Hh];
__device__ float d_gcv[Bb*Hh];
__device__ float d_havg[Bb*Hh];
__device__ float d_gWg[Bb*H7];
__device__ float d_pnum[Bb*NCH*Hh];
__device__ float d_pden[Bb*NCH*Hh];
__device__ float d_invms[Bb];
// fp16 split activations (hi+lo) / fp16 single-rounded weights (16B aligned)
__device__ __align__(16) __half d_ctx_hi[(size_t)BSR*H3];
__device__ __align__(16) __half d_ctx_lo[(size_t)BSR*H3];
__device__ __align__(16) __half d_h_hi0[BSR*Hh];
__device__ __align__(16) __half d_h_lo0[BSR*Hh];
__device__ __align__(16) __half d_h_hi1[BSR*Hh];
__device__ __align__(16) __half d_h_lo1[BSR*Hh];
__device__ __align__(16) __half d_in_hi[BSR*Hh];
__device__ __align__(16) __half d_in_lo[BSR*Hh];
__device__ __align__(16) __half d_W3T[H7*H3];
__device__ __align__(16) __half d_GhT[Hh*Hh];
__device__ __align__(16) __half d_WiT[H7*Hh];

// ---------------- PTX helpers -----------------------------------------------
__device__ __forceinline__ uint32_t smem_u32(const void* p) {
    uint32_t a;
    asm("{ .reg .u64 t; cvta.to.shared.u64 t, %1; cvt.u32.u64 %0, t; }"
        : "=r"(a) : "l"(p));
    return a;
}
__device__ __forceinline__ void cpasync16(uint32_t dst, const void* src) {
    asm volatile("cp.async.cg.shared.global [%0], [%1], 16;" :: "r"(dst), "l"(src));
}
#define CP_COMMIT() asm volatile("cp.async.commit_group;" ::: "memory")
#define CP_WAIT1()  asm volatile("cp.async.wait_group 1;" ::: "memory")
#define CP_WAIT0()  asm volatile("cp.async.wait_group 0;" ::: "memory")

__device__ __forceinline__ void mma16816(float* c, const uint32_t* a, const uint32_t* b) {
    asm volatile(
        "mma.sync.aligned.m16n8k16.row.col.f32.f16.f16.f32 "
        "{%0,%1,%2,%3}, {%4,%5,%6,%7}, {%8,%9}, {%0,%1,%2,%3};"
        : "+f"(c[0]), "+f"(c[1]), "+f"(c[2]), "+f"(c[3])
        : "r"(a[0]), "r"(a[1]), "r"(a[2]), "r"(a[3]), "r"(b[0]), "r"(b[1]));
}

// ---------------- fp16x2 HMMA GEMM (A split hi/lo, B single fp16) ------------
// C[M,N] = (Ahi+Alo)[M,K] @ B^T, B stored [N,K] K-major fp16.
#define KB 32
#define SA 40                      // padded smem row stride (halves)
#define MTILE (128*SA)
#define STAGE (3*MTILE)            // Ahi, Alo, B
#define HSMEM (2*STAGE*2)          // 61440 bytes

__global__ void __launch_bounds__(256, 2) k_hmma(
    int M, int N, int K,
    const __half* __restrict__ Ahi, const __half* __restrict__ Alo,
    const __half* __restrict__ B,
    const float* __restrict__ bias, const float* __restrict__ add,
    float* __restrict__ C)
{
    extern __shared__ __half sm[];
    int tid = threadIdx.x, wid = tid >> 5, lane = tid & 31;
    int gID = lane >> 2, tg = lane & 3;
    int warp_m = wid >> 2, warp_n = wid & 3;
    int arow0 = blockIdx.y * 128, bcol0 = blockIdx.x * 128;

    const __half* srcs[3] = {
        Ahi + (size_t)arow0 * K, Alo + (size_t)arow0 * K,
        B + (size_t)bcol0 * K };

    float acc[4][4][4];
    #pragma unroll
    for (int mi = 0; mi < 4; mi++)
        #pragma unroll
        for (int ni = 0; ni < 4; ni++)
            #pragma unroll
            for (int q = 0; q < 4; q++) acc[mi][ni][q] = 0.f;

    uint32_t smbase = smem_u32(sm);
    int niter = K / KB;

    // prologue: stage 0
    #pragma unroll
    for (int t = 0; t < 3; t++) {
        const __half* src = srcs[t];
        uint32_t dst = smbase + (0 * STAGE + t * MTILE) * 2;
        #pragma unroll
        for (int s = 0; s < 2; s++) {
            int slot = tid + s * 256;
            int row = slot >> 2, cg = (slot & 3) * 8;
            cpasync16(dst + (row * SA + cg) * 2, src + (size_t)row * K + cg);
        }
    }
    CP_COMMIT();

    for (int it = 0; it < niter; it++) {
        if (it + 1 < niter) {
            int st = (it + 1) & 1;
            int k0 = (it + 1) * KB;
            #pragma unroll
            for (int t = 0; t < 3; t++) {
                const __half* src = srcs[t] + k0;
                uint32_t dst = smbase + (st * STAGE + t * MTILE) * 2;
                #pragma unroll
                for (int s = 0; s < 2; s++) {
                    int slot = tid + s * 256;
                    int row = slot >> 2, cg = (slot & 3) * 8;
                    cpasync16(dst + (row * SA + cg) * 2, src + (size_t)row * K + cg);
                }
            }
            CP_COMMIT();
            CP_WAIT1();
        } else {
            CP_WAIT0();
        }
        __syncthreads();

        const __half* As_h = sm + (it & 1) * STAGE;
        const __half* As_l = As_h + MTILE;
        const __half* Bs   = As_h + 2 * MTILE;

        #pragma unroll
        for (int kk = 0; kk < KB; kk += 16) {
            uint32_t bf[4][2];
            #pragma unroll
            for (int ni = 0; ni < 4; ni++) {
                int n = warp_n * 32 + ni * 8 + gID;
                const __half* pb = Bs + n * SA + kk + tg * 2;
                bf[ni][0] = *(const uint32_t*)pb;
                bf[ni][1] = *(const uint32_t*)(pb + 8);
            }
            #pragma unroll
            for (int mi = 0; mi < 4; mi++) {
                int r0 = warp_m * 64 + mi * 16 + gID;
                const __half* ah_ = As_h + r0 * SA + kk + tg * 2;
                const __half* al_ = As_l + r0 * SA + kk + tg * 2;
                uint32_t ah[4], al[4];
                ah[0] = *(const uint32_t*)ah_;
                ah[1] = *(const uint32_t*)(ah_ + 8 * SA);
                ah[2] = *(const uint32_t*)(ah_ + 8);
                ah[3] = *(const uint32_t*)(ah_ + 8 * SA + 8);
                al[0] = *(const uint32_t*)al_;
                al[1] = *(const uint32_t*)(al_ + 8 * SA);
                al[2] = *(const uint32_t*)(al_ + 8);
                al[3] = *(const uint32_t*)(al_ + 8 * SA + 8);
                #pragma unroll
                for (int ni = 0; ni < 4; ni++) {
                    mma16816(acc[mi][ni], ah, bf[ni]);
                    mma16816(acc[mi][ni], al, bf[ni]);
                }
            }
        }
        __syncthreads();
    }

    // epilogue: C = acc (+bias[c]) (+add[r,c])
    #pragma unroll
    for (int mi = 0; mi < 4; mi++) {
        #pragma unroll
        for (int ni = 0; ni < 4; ni++) {
            int r = arow0 + warp_m * 64 + mi * 16 + gID;
            int c = bcol0 + warp_n * 32 + ni * 8 + tg * 2;
            float b0 = bias ? bias[c] : 0.f;
            float b1 = bias ? bias[c + 1] : 0.f;
            float2 v0 = make_float2(acc[mi][ni][0] + b0, acc[mi][ni][1] + b1);
            float2 v1 = make_float2(acc[mi][ni][2] + b0, acc[mi][ni][3] + b1);
            if (add) {
                float2 a0 = *(const float2*)(add + (size_t)r * N + c);
                float2 a1 = *(const float2*)(add + (size_t)(r + 8) * N + c);
                v0.x += a0.x; v0.y += a0.y;
                v1.x += a1.x; v1.y += a1.y;
            }
            *(float2*)(C + (size_t)r * N + c) = v0;
            *(float2*)(C + (size_t)(r + 8) * N + c) = v1;
        }
    }
}

// ---------------- helpers ----------------------------------------------------
__device__ __forceinline__ float2 blockSum2(float a, float b, float* sh) {
    #pragma unroll
    for (int o = 16; o > 0; o >>= 1) {
        a += __shfl_down_sync(0xffffffffu, a, o);
        b += __shfl_down_sync(0xffffffffu, b, o);
    }
    int w = threadIdx.x >> 5, l = threadIdx.x & 31;
    if (l == 0) { sh[w] = a; sh[8 + w] = b; }
    __syncthreads();
    if (threadIdx.x == 0) {
        float sa = 0.f, sb2 = 0.f;
        #pragma unroll
        for (int i = 0; i < 8; i++) { sa += sh[i]; sb2 += sh[8 + i]; }
        sh[16] = sa; sh[17] = sb2;
    }
    __syncthreads();
    float2 r = make_float2(sh[16], sh[17]);
    __syncthreads();
    return r;
}
__device__ __forceinline__ float sigmoidf_(float x) { return 1.f / (1.f + expf(-x)); }
__device__ __forceinline__ void splith(float v, __half& hi, __half& lo) {
    hi = __float2half(v);
    lo = __float2half(v - __half2float(hi));
}

// ---------------- split / transpose kernels ----------------------------------
__global__ void k_split(const float* __restrict__ x, __half* __restrict__ hi,
                        __half* __restrict__ lo, int n)
{
    int i = blockIdx.x * blockDim.x + threadIdx.x;
    if (i >= n) return;
    splith(x[i], hi[i], lo[i]);
}

__global__ void k_w3t(const float* __restrict__ Wc, const float* __restrict__ Wh,
                      __half* __restrict__ w)
{
    int i = blockIdx.x * blockDim.x + threadIdx.x;   // [H7 x H3]
    if (i >= H7 * H3) return;
    int n = i / H3, k = i % H3;
    float v = (k < Hh) ? Wc[(size_t)k * H7 + n]
            : (k < 2 * Hh) ? Wh[(size_t)(k - Hh) * H7 + n]
            : Wc[(size_t)(k - Hh) * H7 + n];
    w[i] = __float2half(v);
}

__global__ void k_wt(const float* __restrict__ W, int K, int N,
                     __half* __restrict__ w)
{
    int i = blockIdx.x * blockDim.x + threadIdx.x;   // [N x K]
    if (i >= N * K) return;
    int n = i / K, k = i % K;
    w[i] = __float2half(W[(size_t)k * N + n]);
}

// ---------------- tiny GEMM for M=8 rows -------------------------------------
__global__ void k_smallgemm(int M, int N, int K,
                            const float* __restrict__ A, const float* __restrict__ W,
                            const float* __restrict__ bias, float* __restrict__ C)
{
    int idx = blockIdx.x * blockDim.x + threadIdx.x;
    if (idx >= M * N) return;
    int m = idx / N, n = idx % N;
    float acc = bias ? bias[n] : 0.f;
    const float* a = A + (size_t)m * K;
    for (int k = 0; k < K; k++) acc += a[k] * W[(size_t)k * N + n];
    C[idx] = acc;
}

// ---------------- small kernels ----------------------------------------------
__global__ void k_invms(const float* __restrict__ mask, float* __restrict__ invms)
{
    __shared__ float sh[8];
    int b = blockIdx.x, t = threadIdx.x;
    float a = 0.f;
    for (int s = t; s < Ss; s += 256) a += mask[b * Ss + s];
    #pragma unroll
    for (int o = 16; o > 0; o >>= 1) a += __shfl_down_sync(0xffffffffu, a, o);
    if ((t & 31) == 0) sh[t >> 5] = a;
    __syncthreads();
    if (t == 0) {
        float s2 = 0.f;
        #pragma unroll
        for (int i = 0; i < 8; i++) s2 += sh[i];
        invms[b] = 1.f / s2;
    }
}

__global__ void k_meanp(const float* __restrict__ x, const float* __restrict__ mask,
                        float* __restrict__ pnum)
{
    int ch = blockIdx.x, b = blockIdx.y, h = threadIdx.x;
    float acc = 0.f;
    int s0 = ch * SCH;
    #pragma unroll
    for (int i = 0; i < SCH; i++) {
        int s = s0 + i;
        acc += x[((size_t)(b * Ss + s)) * Hh + h] * mask[b * Ss + s];
    }
    pnum[(b * NCH + ch) * Hh + h] = acc;
}

__global__ void k_meanf(const float* __restrict__ pnum, const float* __restrict__ invms,
                        float* __restrict__ out)
{
    int b = blockIdx.x, h = threadIdx.x;
    float a = 0.f;
    #pragma unroll
    for (int c = 0; c < NCH; c++) a += pnum[(b * NCH + c) * Hh + h];
    out[b * Hh + h] = a * invms[b];
}

__global__ void k_igog(const float* __restrict__ pi, const float* __restrict__ pa,
                       const float* __restrict__ lns, const float* __restrict__ lnb,
                       float* __restrict__ ig, float* __restrict__ og)
{
    __shared__ float sh[18];
    int b = blockIdx.x, h = threadIdx.x;
    float v = pi[b * H3 + h] + pa[b * 2 * Hh + h];
    float2 ssum = blockSum2(v, v * v, sh);
    float m = ssum.x * (1.f / 256.f);
    float var = (ssum.y - 256.f * m * m) * (1.f / 255.f);
    float zn = lns[h] * (v - m) * rsqrtf(var + 1e-6f) + lnb[h];
    ig[b * Hh + h] = sigmoidf_(zn);
    v = pi[b * H3 + 2 * Hh + h] + pa[b * 2 * Hh + Hh + h];
    ssum = blockSum2(v, v * v, sh);
    m = ssum.x * (1.f / 256.f);
    var = (ssum.y - 256.f * m * m) * (1.f / 255.f);
    zn = lns[2 * Hh + h] * (v - m) * rsqrtf(var + 1e-6f) + lnb[2 * Hh + h];
    og[b * Hh + h] = sigmoidf_(zn);
}

// fused hg + gcp
__global__ __launch_bounds__(256) void k_hgcp(
    const float* __restrict__ ph, const float* __restrict__ pi,
    const float* __restrict__ mask,
    const float* __restrict__ lns, const float* __restrict__ lnb,
    const float* __restrict__ cell,
    float* __restrict__ pnum, float* __restrict__ pden)
{
    __shared__ float wsum[8][32];
    __shared__ float fin[32];
    int ch = blockIdx.x, b = blockIdx.y, h = threadIdx.x;
    int w = h >> 5, lane = h & 31;
    int s0 = ch * SCH;
    float piv = pi[b * H3 + Hh + h];
    float v[SCH];
    #pragma unroll
    for (int i = 0; i < SCH; i++)
        v[i] = ph[((size_t)(b * Ss + s0 + i)) * Hh + h] + piv;

    float p[2 * SCH];
    #pragma unroll
    for (int i = 0; i < SCH; i++) { p[2 * i] = v[i]; p[2 * i + 1] = v[i] * v[i]; }
    #pragma unroll
    for (int o = 16; o > 0; o >>= 1)
        #pragma unroll
        for (int j = 0; j < 2 * SCH; j++)
            p[j] += __shfl_down_sync(0xffffffffu, p[j], o);
    if (lane == 0)
        #pragma unroll
        for (int j = 0; j < 2 * SCH; j++) wsum[w][j] = p[j];
    __syncthreads();
    if (h < 2 * SCH) {
        float a = 0.f;
        #pragma unroll
        for (int i = 0; i < 8; i++) a += wsum[i][h];
        fin[h] = a;
    }
    __syncthreads();

    float lnsv = lns[Hh + h], lnbv = lnb[Hh + h];
    float num = 0.f, den = 0.f;
    #pragma unroll
    for (int i = 0; i < SCH; i++) {
        float m = fin[2 * i] * (1.f / 256.f);
        float var = (fin[2 * i + 1] - 256.f * m * m) * (1.f / 255.f);
        float zn = lnsv * (v[i] - m) * rsqrtf(var + 1e-6f) + lnbv;
        float mk = mask[b * Ss + s0 + i];
        float e = expf(sigmoidf_(zn) + (mk * 1e25f - 1e25f));
        size_t idx = ((size_t)(b * Ss + s0 + i)) * Hh + h;
        num += e * cell[idx];
        den += e;
    }
    pnum[(b * NCH + ch) * Hh + h] = num;
    pden[(b * NCH + ch) * Hh + h] = den;
}

__global__ void k_gcf(const float* __restrict__ pnum, const float* __restrict__ pden,
                      const float* __restrict__ ig, const float* __restrict__ og,
                      float* __restrict__ gc, float* __restrict__ gh)
{
    int b = blockIdx.x, h = threadIdx.x;
    float num = 0.f, den = 0.f;
    #pragma unroll
    for (int c = 0; c < NCH; c++) {
        num += pnum[(b * NCH + c) * Hh + h];
        den += pden[(b * NCH + c) * Hh + h];
    }
    float ei = expf(ig[b * Hh + h]);
    float g = (gc[b * Hh + h] * ei + num) / (ei + den);
    gc[b * Hh + h] = g;
    gh[b * Hh + h] = og[b * Hh + h] * tanhf(g);
}

// build split-fp16 ctx = [h_l, h, h_r] from split-fp16 hidden
__global__ void k_ctx_bf(const __half* __restrict__ hhi,
                         const __half* __restrict__ hlo,
                         __half* __restrict__ chi,
                         __half* __restrict__ clo)
{
    int i = blockIdx.x * blockDim.x + threadIdx.x;  // 8-elem chunk
    if (i >= BSR * (H3 / 8)) return;
    int bs = i / (H3 / 8);
    int j = (i % (H3 / 8)) * 8;
    int s = bs & (Ss - 1);
    uint4 vh = make_uint4(0, 0, 0, 0), vl = make_uint4(0, 0, 0, 0);
    long off = -1;
    if (j < Hh)           { if (s > 0)      off = ((long)bs - 1) * Hh + j; }
    else if (j < 2 * Hh)  {                 off = (long)bs * Hh + (j - Hh); }
    else                  { if (s < Ss - 1) off = ((long)bs + 1) * Hh + (j - 2 * Hh); }
    if (off >= 0) {
        vh = *(const uint4*)(hhi + off);
        vl = *(const uint4*)(hlo + off);
    }
    *(uint4*)(chi + (size_t)bs * H3 + j) = vh;
    *(uint4*)(clo + (size_t)bs * H3 + j) = vl;
}

// one-pass LN for all 7 groups; z already contains proj
__global__ __launch_bounds__(256) void k_update(
    const float* __restrict__ z,
    const float* __restrict__ gWg, const float* __restrict__ gc,
    const float* __restrict__ mask,
    const float* __restrict__ lns, const float* __restrict__ lnb,
    const float* __restrict__ c_old,
    float* __restrict__ h_new, float* __restrict__ c_new,
    __half* __restrict__ hhi, __half* __restrict__ hlo)
{
    __shared__ float wsum[8][14];
    __shared__ float fin[14];
    int bs = blockIdx.x; int b = bs >> 10; int s = bs & (Ss - 1);
    int h = threadIdx.x;
    int w = h >> 5, lane = h & 31;
    size_t rz = (size_t)bs * H7;
    float v[7];
    #pragma unroll
    for (int k = 0; k < 7; k++)
        v[k] = z[rz + k * Hh + h] + gWg[b * H7 + k * Hh + h];

    float p[14];
    #pragma unroll
    for (int k = 0; k < 7; k++) { p[2 * k] = v[k]; p[2 * k + 1] = v[k] * v[k]; }
    #pragma unroll
    for (int o = 16; o > 0; o >>= 1)
        #pragma unroll
        for (int j = 0; j < 14; j++)
            p[j] += __shfl_down_sync(0xffffffffu, p[j], o);
    if (lane == 0)
        #pragma unroll
        for (int j = 0; j < 14; j++) wsum[w][j] = p[j];
    __syncthreads();
    if (h < 14) {
        float a = 0.f;
        #pragma unroll
        for (int i = 0; i < 8; i++) a += wsum[i][h];
        fin[h] = a;
    }
    __syncthreads();

    float zn[7];
    #pragma unroll
    for (int k = 0; k < 7; k++) {
        float m = fin[2 * k] * (1.f / 256.f);
        float var = (fin[2 * k + 1] - 256.f * m * m) * (1.f / 255.f);
        zn[k] = lns[(3 + k) * Hh + h] * (v[k] - m) * rsqrtf(var + 1e-6f) + lnb[(3 + k) * Hh + h];
    }
    float e[6], den = 0.f;
    #pragma unroll
    for (int k = 0; k < 6; k++) {
        e[k] = expf(sigmoidf_(zn[k]));
        den += e[k];
    }
    float inv = 1.f / den;
    float mem = tanhf(zn[6]);
    size_t idx = (size_t)bs * Hh + h;
    float c  = c_old[idx];
    float cl = (s > 0)      ? c_old[idx - Hh] : 0.f;
    float cr = (s < Ss - 1) ? c_old[idx + Hh] : 0.f;
    float cn = (e[1] * cl + e[2] * cr + e[3] * c + e[0] * mem + e[4] * gc[b * Hh + h]) * inv;
    float mk = mask[bs];
    float hv = e[5] * inv * tanhf(cn) * mk;
    h_new[idx] = hv;
    c_new[idx] = cn * mk;
    splith(hv, hhi[idx], hlo[idx]);
}

// ---------------- orchestration ----------------------------------------------
extern "C" void kernel_launch(void* const* d_in, const int* in_sizes, int n_in,
                              void* d_out, int out_size)
{
    (void)in_sizes; (void)n_in; (void)out_size;
    const float* inputs = (const float*)d_in[0];
    const float* mask   = (const float*)d_in[1];
    const float* ih     = (const float*)d_in[2];
    const float* ic     = (const float*)d_in[3];
    const float* Wc     = (const float*)d_in[4];
    const float* Wh     = (const float*)d_in[5];
    const float* Wi     = (const float*)d_in[6];
    const float* bi     = (const float*)d_in[7];
    const float* Wg     = (const float*)d_in[8];
    const float* Gi     = (const float*)d_in[9];
    const float* gb     = (const float*)d_in[10];
    const float* Gh     = (const float*)d_in[11];
    const float* Ga     = (const float*)d_in[12];
    const float* lns    = (const float*)d_in[13];
    const float* lnb    = (const float*)d_in[14];
    float* out = (float*)d_out;

    float *hb0, *hb1, *cb0, *cb1, *proj, *zb, *ph;
    float *pi, *pa, *ig, *og, *gh, *gc, *havg, *gWg, *pnum, *pden, *invms;
    __half *chi, *clo, *hh0, *hl0, *hh1, *hl1, *inh, *inl;
    __half *w3, *ght, *wit;
    cudaGetSymbolAddress((void**)&hb0,  d_hbuf0);
    cudaGetSymbolAddress((void**)&hb1,  d_hbuf1);
    cudaGetSymbolAddress((void**)&cb0,  d_cbuf0);
    cudaGetSymbolAddress((void**)&cb1,  d_cbuf1);
    cudaGetSymbolAddress((void**)&proj, d_proj);
    cudaGetSymbolAddress((void**)&zb,   d_zbuf);
    cudaGetSymbolAddress((void**)&ph,   d_ph);
    cudaGetSymbolAddress((void**)&pi,   d_pi);
    cudaGetSymbolAddress((void**)&pa,   d_pa);
    cudaGetSymbolAddress((void**)&ig,   d_igb);
    cudaGetSymbolAddress((void**)&og,   d_ogb);
    cudaGetSymbolAddress((void**)&gh,   d_gh);
    cudaGetSymbolAddress((void**)&gc,   d_gcv);
    cudaGetSymbolAddress((void**)&havg, d_havg);
    cudaGetSymbolAddress((void**)&gWg,  d_gWg);
    cudaGetSymbolAddress((void**)&pnum, d_pnum);
    cudaGetSymbolAddress((void**)&pden, d_pden);
    cudaGetSymbolAddress((void**)&invms, d_invms);
    cudaGetSymbolAddress((void**)&chi, d_ctx_hi);
    cudaGetSymbolAddress((void**)&clo, d_ctx_lo);
    cudaGetSymbolAddress((void**)&hh0, d_h_hi0);
    cudaGetSymbolAddress((void**)&hl0, d_h_lo0);
    cudaGetSymbolAddress((void**)&hh1, d_h_hi1);
    cudaGetSymbolAddress((void**)&hl1, d_h_lo1);
    cudaGetSymbolAddress((void**)&inh, d_in_hi);
    cudaGetSymbolAddress((void**)&inl, d_in_lo);
    cudaGetSymbolAddress((void**)&w3,  d_W3T);
    cudaGetSymbolAddress((void**)&ght, d_GhT);
    cudaGetSymbolAddress((void**)&wit, d_WiT);

    cudaFuncSetAttribute(k_hmma, cudaFuncAttributeMaxDynamicSharedMemorySize, HSMEM);

    static cudaStream_t s2 = [] {
        cudaStream_t s; cudaStreamCreateWithFlags(&s, cudaStreamNonBlocking); return s;
    }();
    static cudaStream_t s3 = [] {
        cudaStream_t s; cudaStreamCreateWithFlags(&s, cudaStreamNonBlocking); return s;
    }();
    static cudaEvent_t evFork = [] {
        cudaEvent_t e; cudaEventCreateWithFlags(&e, cudaEventDisableTiming); return e;
    }();
    static cudaEvent_t evJoin = [] {
        cudaEvent_t e; cudaEventCreateWithFlags(&e, cudaEventDisableTiming); return e;
    }();
    static cudaEvent_t evPh = [] {
        cudaEvent_t e; cudaEventCreateWithFlags(&e, cudaEventDisableTiming); return e;
    }();

    // layer-invariant precompute (main stream)
    k_invms<<<Bb, 256>>>(mask, invms);
    k_meanp<<<dim3(NCH, Bb), 256>>>(ih, mask, pnum);
    k_meanf<<<Bb, 256>>>(pnum, invms, gh);
    k_meanp<<<dim3(NCH, Bb), 256>>>(ic, mask, pnum);
    k_meanf<<<Bb, 256>>>(pnum, invms, gc);
    k_w3t<<<(H7 * H3 + 255) / 256, 256>>>(Wc, Wh, w3);
    k_wt<<<(Hh * Hh + 255) / 256, 256>>>(Gh, Hh, Hh, ght);
    k_wt<<<(H7 * Hh + 255) / 256, 256>>>(Wi, Hh, H7, wit);
    k_split<<<(BSR * Hh + 255) / 256, 256>>>(ih, hh0, hl0, BSR * Hh);
    k_split<<<(BSR * Hh + 255) / 256, 256>>>(inputs, inh, inl, BSR * Hh);
    k_hmma<<<dim3(H7 / 128, BSR / 128), 256, HSMEM>>>(
        BSR, H7, Hh, inh, inl, wit, bi, (const float*)nullptr, proj);

    float* hbufs[2] = { hb0, hb1 };
    float* cbufs[2] = { cb0, cb1 };
    __half* hhis[2] = { hh0, hh1 };
    __half* hlos[2] = { hl0, hl1 };

    for (int l = 0; l < LL; l++) {
        const float* hid = (l == 0) ? ih : hbufs[l & 1];
        const float* cel = (l == 0) ? ic : cbufs[l & 1];
        const __half* hhi = hhis[l & 1];
        const __half* hlo = hlos[l & 1];
        float* hout = (l == LL - 1) ? out : hbufs[(l + 1) & 1];
        float* cout = cbufs[(l + 1) & 1];

        // fork: both GEMM branches depend only on hidden from prev update
        cudaEventRecord(evFork, 0);
        // s2: z-branch (ctx + z-GEMM, proj fused into epilogue)
        cudaStreamWaitEvent(s2, evFork, 0);
        k_ctx_bf<<<(BSR * (H3 / 8) + 255) / 256, 256, 0, s2>>>(hhi, hlo, chi, clo);
        k_hmma<<<dim3(H7 / 128, BSR / 128), 256, HSMEM, s2>>>(
            BSR, H7, H3, chi, clo, w3, (const float*)nullptr, proj, zb);
        cudaEventRecord(evJoin, s2);
        // s3: ph-branch (hidden @ Gh)
        cudaStreamWaitEvent(s3, evFork, 0);
        k_hmma<<<dim3(Hh / 128, BSR / 128), 256, HSMEM, s3>>>(
            BSR, Hh, Hh, hhi, hlo, ght,
            (const float*)nullptr, (const float*)nullptr, ph);
        cudaEventRecord(evPh, s3);

        // ---- global state chain (main stream, concurrent with both) ----
        k_meanp<<<dim3(NCH, Bb), 256>>>(hid, mask, pnum);
        k_meanf<<<Bb, 256>>>(pnum, invms, havg);
        k_smallgemm<<<(Bb * H3 + 255) / 256, 256>>>(Bb, H3, Hh, gh, Gi, gb, pi);
        k_smallgemm<<<(Bb * 2 * Hh + 255) / 256, 256>>>(Bb, 2 * Hh, Hh, havg, Ga,
                                                        (const float*)nullptr, pa);
        k_igog<<<Bb, 256>>>(pi, pa, lns, lnb, ig, og);
        cudaStreamWaitEvent(0, evPh, 0);
        k_hgcp<<<dim3(NCH, Bb), 256>>>(ph, pi, mask, lns, lnb, cel, pnum, pden);
        k_gcf<<<Bb, 256>>>(pnum, pden, ig, og, gc, gh);
        k_smallgemm<<<(Bb * H7 + 255) / 256, 256>>>(Bb, H7, Hh, gh, Wg,
                                                    (const float*)nullptr, gWg);

        // join: update needs z (s2) + gWg/gc (main)
        cudaStreamWaitEvent(0, evJoin, 0);
        k_update<<<BSR, 256>>>(zb, gWg, gc, mask, lns, lnb, cel, hout, cout,
                               hhis[(l + 1) & 1], hlos[(l + 1) & 1]);
    }
}

// round 14
// speedup vs baseline: 1.2013x; 1.2013x over previous
#include <cuda_runtime.h>
#include <cuda_fp16.h>
#include <cstdint>
#include <cstddef>

// Problem constants
#define Bb 8
#define Ss 1024
#define Hh 256
#define LL 7
#define BSR (Bb*Ss)        // 8192 rows
#define H7 (7*Hh)          // 1792
#define H3 (3*Hh)          // 768
#define NCH 64
#define SCH (Ss/NCH)       // 16

// ---------------- scratch (device globals; no allocations allowed) ----------
__device__ float d_hbuf0[BSR*Hh];
__device__ float d_hbuf1[BSR*Hh];
__device__ float d_cbuf0[BSR*Hh];
__device__ float d_cbuf1[BSR*Hh];
__device__ float d_proj[(size_t)BSR*H7];
__device__ float d_zbuf[(size_t)BSR*H7];
__device__ float d_ph[BSR*Hh];
__device__ float d_pi[Bb*H3];
__device__ float d_pa[Bb*2*Hh];
__device__ float d_igb[Bb*Hh];
__device__ float d_ogb[Bb*Hh];
__device__ float d_gh[Bb*Hh];
__device__ float d_gcv[Bb*Hh];
__device__ float d_havg[Bb*Hh];
__device__ float d_gWg[Bb*H7];
__device__ float d_pnum[Bb*NCH*Hh];
__device__ float d_pden[Bb*NCH*Hh];
__device__ float d_invms[Bb];
// fp16 activations / weights (single-rounded; 16B aligned)
__device__ __align__(16) __half d_ctx_h[(size_t)BSR*H3];
__device__ __align__(16) __half d_h_f0[BSR*Hh];
__device__ __align__(16) __half d_h_f1[BSR*Hh];
__device__ __align__(16) __half d_in_f[BSR*Hh];
__device__ __align__(16) __half d_W3T[H7*H3];
__device__ __align__(16) __half d_GhT[Hh*Hh];
__device__ __align__(16) __half d_WiT[H7*Hh];

// ---------------- PTX helpers -----------------------------------------------
__device__ __forceinline__ uint32_t smem_u32(const void* p) {
    uint32_t a;
    asm("{ .reg .u64 t; cvta.to.shared.u64 t, %1; cvt.u32.u64 %0, t; }"
        : "=r"(a) : "l"(p));
    return a;
}
__device__ __forceinline__ void cpasync16(uint32_t dst, const void* src) {
    asm volatile("cp.async.cg.shared.global [%0], [%1], 16;" :: "r"(dst), "l"(src));
}
#define CP_COMMIT() asm volatile("cp.async.commit_group;" ::: "memory")
#define CP_WAIT1()  asm volatile("cp.async.wait_group 1;" ::: "memory")
#define CP_WAIT0()  asm volatile("cp.async.wait_group 0;" ::: "memory")

__device__ __forceinline__ void mma16816(float* c, const uint32_t* a, const uint32_t* b) {
    asm volatile(
        "mma.sync.aligned.m16n8k16.row.col.f32.f16.f16.f32 "
        "{%0,%1,%2,%3}, {%4,%5,%6,%7}, {%8,%9}, {%0,%1,%2,%3};"
        : "+f"(c[0]), "+f"(c[1]), "+f"(c[2]), "+f"(c[3])
        : "r"(a[0]), "r"(a[1]), "r"(a[2]), "r"(a[3]), "r"(b[0]), "r"(b[1]));
}

// ---------------- fp16 HMMA GEMM (A and B single fp16) -----------------------
// C[M,N] = A[M,K] @ B^T, B stored [N,K] K-major fp16.
#define KB 32
#define SA 40                      // padded smem row stride (halves)
#define MTILE (128*SA)
#define STAGE (2*MTILE)            // A, B
#define HSMEM (2*STAGE*2)          // 40960 bytes

__global__ void __launch_bounds__(256, 2) k_hmma(
    int M, int N, int K,
    const __half* __restrict__ A, const __half* __restrict__ B,
    const float* __restrict__ bias, const float* __restrict__ add,
    float* __restrict__ C)
{
    extern __shared__ __half sm[];
    int tid = threadIdx.x, wid = tid >> 5, lane = tid & 31;
    int gID = lane >> 2, tg = lane & 3;
    int warp_m = wid >> 2, warp_n = wid & 3;
    int arow0 = blockIdx.y * 128, bcol0 = blockIdx.x * 128;

    const __half* srcs[2] = { A + (size_t)arow0 * K, B + (size_t)bcol0 * K };

    float acc[4][4][4];
    #pragma unroll
    for (int mi = 0; mi < 4; mi++)
        #pragma unroll
        for (int ni = 0; ni < 4; ni++)
            #pragma unroll
            for (int q = 0; q < 4; q++) acc[mi][ni][q] = 0.f;

    uint32_t smbase = smem_u32(sm);
    int niter = K / KB;

    // prologue: stage 0
    #pragma unroll
    for (int t = 0; t < 2; t++) {
        const __half* src = srcs[t];
        uint32_t dst = smbase + (0 * STAGE + t * MTILE) * 2;
        #pragma unroll
        for (int s = 0; s < 2; s++) {
            int slot = tid + s * 256;
            int row = slot >> 2, cg = (slot & 3) * 8;
            cpasync16(dst + (row * SA + cg) * 2, src + (size_t)row * K + cg);
        }
    }
    CP_COMMIT();

    for (int it = 0; it < niter; it++) {
        if (it + 1 < niter) {
            int st = (it + 1) & 1;
            int k0 = (it + 1) * KB;
            #pragma unroll
            for (int t = 0; t < 2; t++) {
                const __half* src = srcs[t] + k0;
                uint32_t dst = smbase + (st * STAGE + t * MTILE) * 2;
                #pragma unroll
                for (int s = 0; s < 2; s++) {
                    int slot = tid + s * 256;
                    int row = slot >> 2, cg = (slot & 3) * 8;
                    cpasync16(dst + (row * SA + cg) * 2, src + (size_t)row * K + cg);
                }
            }
            CP_COMMIT();
            CP_WAIT1();
        } else {
            CP_WAIT0();
        }
        __syncthreads();

        const __half* As = sm + (it & 1) * STAGE;
        const __half* Bs = As + MTILE;

        #pragma unroll
        for (int kk = 0; kk < KB; kk += 16) {
            uint32_t bf[4][2];
            #pragma unroll
            for (int ni = 0; ni < 4; ni++) {
                int n = warp_n * 32 + ni * 8 + gID;
                const __half* pb = Bs + n * SA + kk + tg * 2;
                bf[ni][0] = *(const uint32_t*)pb;
                bf[ni][1] = *(const uint32_t*)(pb + 8);
            }
            #pragma unroll
            for (int mi = 0; mi < 4; mi++) {
                int r0 = warp_m * 64 + mi * 16 + gID;
                const __half* pa_ = As + r0 * SA + kk + tg * 2;
                uint32_t af[4];
                af[0] = *(const uint32_t*)pa_;
                af[1] = *(const uint32_t*)(pa_ + 8 * SA);
                af[2] = *(const uint32_t*)(pa_ + 8);
                af[3] = *(const uint32_t*)(pa_ + 8 * SA + 8);
                #pragma unroll
                for (int ni = 0; ni < 4; ni++)
                    mma16816(acc[mi][ni], af, bf[ni]);
            }
        }
        __syncthreads();
    }

    // epilogue: C = acc (+bias[c]) (+add[r,c])
    #pragma unroll
    for (int mi = 0; mi < 4; mi++) {
        #pragma unroll
        for (int ni = 0; ni < 4; ni++) {
            int r = arow0 + warp_m * 64 + mi * 16 + gID;
            int c = bcol0 + warp_n * 32 + ni * 8 + tg * 2;
            float b0 = bias ? bias[c] : 0.f;
            float b1 = bias ? bias[c + 1] : 0.f;
            float2 v0 = make_float2(acc[mi][ni][0] + b0, acc[mi][ni][1] + b1);
            float2 v1 = make_float2(acc[mi][ni][2] + b0, acc[mi][ni][3] + b1);
            if (add) {
                float2 a0 = *(const float2*)(add + (size_t)r * N + c);
                float2 a1 = *(const float2*)(add + (size_t)(r + 8) * N + c);
                v0.x += a0.x; v0.y += a0.y;
                v1.x += a1.x; v1.y += a1.y;
            }
            *(float2*)(C + (size_t)r * N + c) = v0;
            *(float2*)(C + (size_t)(r + 8) * N + c) = v1;
        }
    }
}

// ---------------- helpers ----------------------------------------------------
__device__ __forceinline__ float2 blockSum2(float a, float b, float* sh) {
    #pragma unroll
    for (int o = 16; o > 0; o >>= 1) {
        a += __shfl_down_sync(0xffffffffu, a, o);
        b += __shfl_down_sync(0xffffffffu, b, o);
    }
    int w = threadIdx.x >> 5, l = threadIdx.x & 31;
    if (l == 0) { sh[w] = a; sh[8 + w] = b; }
    __syncthreads();
    if (threadIdx.x == 0) {
        float sa = 0.f, sb2 = 0.f;
        #pragma unroll
        for (int i = 0; i < 8; i++) { sa += sh[i]; sb2 += sh[8 + i]; }
        sh[16] = sa; sh[17] = sb2;
    }
    __syncthreads();
    float2 r = make_float2(sh[16], sh[17]);
    __syncthreads();
    return r;
}
__device__ __forceinline__ float sigmoidf_(float x) { return 1.f / (1.f + expf(-x)); }

// ---------------- cast / transpose kernels -----------------------------------
__global__ void k_cast(const float* __restrict__ x, __half* __restrict__ y, int n)
{
    int i = blockIdx.x * blockDim.x + threadIdx.x;
    if (i >= n) return;
    y[i] = __float2half(x[i]);
}

__global__ void k_w3t(const float* __restrict__ Wc, const float* __restrict__ Wh,
                      __half* __restrict__ w)
{
    int i = blockIdx.x * blockDim.x + threadIdx.x;   // [H7 x H3]
    if (i >= H7 * H3) return;
    int n = i / H3, k = i % H3;
    float v = (k < Hh) ? Wc[(size_t)k * H7 + n]
            : (k < 2 * Hh) ? Wh[(size_t)(k - Hh) * H7 + n]
            : Wc[(size_t)(k - Hh) * H7 + n];
    w[i] = __float2half(v);
}

__global__ void k_wt(const float* __restrict__ W, int K, int N,
                     __half* __restrict__ w)
{
    int i = blockIdx.x * blockDim.x + threadIdx.x;   // [N x K]
    if (i >= N * K) return;
    int n = i / K, k = i % K;
    w[i] = __float2half(W[(size_t)k * N + n]);
}

// ---------------- tiny GEMM for M=8 rows -------------------------------------
__global__ void k_smallgemm(int M, int N, int K,
                            const float* __restrict__ A, const float* __restrict__ W,
                            const float* __restrict__ bias, float* __restrict__ C)
{
    int idx = blockIdx.x * blockDim.x + threadIdx.x;
    if (idx >= M * N) return;
    int m = idx / N, n = idx % N;
    float acc = bias ? bias[n] : 0.f;
    const float* a = A + (size_t)m * K;
    for (int k = 0; k < K; k++) acc += a[k] * W[(size_t)k * N + n];
    C[idx] = acc;
}

// ---------------- small kernels ----------------------------------------------
__global__ void k_invms(const float* __restrict__ mask, float* __restrict__ invms)
{
    __shared__ float sh[8];
    int b = blockIdx.x, t = threadIdx.x;
    float a = 0.f;
    for (int s = t; s < Ss; s += 256) a += mask[b * Ss + s];
    #pragma unroll
    for (int o = 16; o > 0; o >>= 1) a += __shfl_down_sync(0xffffffffu, a, o);
    if ((t & 31) == 0) sh[t >> 5] = a;
    __syncthreads();
    if (t == 0) {
        float s2 = 0.f;
        #pragma unroll
        for (int i = 0; i < 8; i++) s2 += sh[i];
        invms[b] = 1.f / s2;
    }
}

__global__ void k_meanp(const float* __restrict__ x, const float* __restrict__ mask,
                        float* __restrict__ pnum)
{
    int ch = blockIdx.x, b = blockIdx.y, h = threadIdx.x;
    float acc = 0.f;
    int s0 = ch * SCH;
    #pragma unroll
    for (int i = 0; i < SCH; i++) {
        int s = s0 + i;
        acc += x[((size_t)(b * Ss + s)) * Hh + h] * mask[b * Ss + s];
    }
    pnum[(b * NCH + ch) * Hh + h] = acc;
}

__global__ void k_meanf(const float* __restrict__ pnum, const float* __restrict__ invms,
                        float* __restrict__ out)
{
    int b = blockIdx.x, h = threadIdx.x;
    float a = 0.f;
    #pragma unroll
    for (int c = 0; c < NCH; c++) a += pnum[(b * NCH + c) * Hh + h];
    out[b * Hh + h] = a * invms[b];
}

__global__ void k_igog(const float* __restrict__ pi, const float* __restrict__ pa,
                       const float* __restrict__ lns, const float* __restrict__ lnb,
                       float* __restrict__ ig, float* __restrict__ og)
{
    __shared__ float sh[18];
    int b = blockIdx.x, h = threadIdx.x;
    float v = pi[b * H3 + h] + pa[b * 2 * Hh + h];
    float2 ssum = blockSum2(v, v * v, sh);
    float m = ssum.x * (1.f / 256.f);
    float var = (ssum.y - 256.f * m * m) * (1.f / 255.f);
    float zn = lns[h] * (v - m) * rsqrtf(var + 1e-6f) + lnb[h];
    ig[b * Hh + h] = sigmoidf_(zn);
    v = pi[b * H3 + 2 * Hh + h] + pa[b * 2 * Hh + Hh + h];
    ssum = blockSum2(v, v * v, sh);
    m = ssum.x * (1.f / 256.f);
    var = (ssum.y - 256.f * m * m) * (1.f / 255.f);
    zn = lns[2 * Hh + h] * (v - m) * rsqrtf(var + 1e-6f) + lnb[2 * Hh + h];
    og[b * Hh + h] = sigmoidf_(zn);
}

// fused hg + gcp
__global__ __launch_bounds__(256) void k_hgcp(
    const float* __restrict__ ph, const float* __restrict__ pi,
    const float* __restrict__ mask,
    const float* __restrict__ lns, const float* __restrict__ lnb,
    const float* __restrict__ cell,
    float* __restrict__ pnum, float* __restrict__ pden)
{
    __shared__ float wsum[8][32];
    __shared__ float fin[32];
    int ch = blockIdx.x, b = blockIdx.y, h = threadIdx.x;
    int w = h >> 5, lane = h & 31;
    int s0 = ch * SCH;
    float piv = pi[b * H3 + Hh + h];
    float v[SCH];
    #pragma unroll
    for (int i = 0; i < SCH; i++)
        v[i] = ph[((size_t)(b * Ss + s0 + i)) * Hh + h] + piv;

    float p[2 * SCH];
    #pragma unroll
    for (int i = 0; i < SCH; i++) { p[2 * i] = v[i]; p[2 * i + 1] = v[i] * v[i]; }
    #pragma unroll
    for (int o = 16; o > 0; o >>= 1)
        #pragma unroll
        for (int j = 0; j < 2 * SCH; j++)
            p[j] += __shfl_down_sync(0xffffffffu, p[j], o);
    if (lane == 0)
        #pragma unroll
        for (int j = 0; j < 2 * SCH; j++) wsum[w][j] = p[j];
    __syncthreads();
    if (h < 2 * SCH) {
        float a = 0.f;
        #pragma unroll
        for (int i = 0; i < 8; i++) a += wsum[i][h];
        fin[h] = a;
    }
    __syncthreads();

    float lnsv = lns[Hh + h], lnbv = lnb[Hh + h];
    float num = 0.f, den = 0.f;
    #pragma unroll
    for (int i = 0; i < SCH; i++) {
        float m = fin[2 * i] * (1.f / 256.f);
        float var = (fin[2 * i + 1] - 256.f * m * m) * (1.f / 255.f);
        float zn = lnsv * (v[i] - m) * rsqrtf(var + 1e-6f) + lnbv;
        float mk = mask[b * Ss + s0 + i];
        float e = expf(sigmoidf_(zn) + (mk * 1e25f - 1e25f));
        size_t idx = ((size_t)(b * Ss + s0 + i)) * Hh + h;
        num += e * cell[idx];
        den += e;
    }
    pnum[(b * NCH + ch) * Hh + h] = num;
    pden[(b * NCH + ch) * Hh + h] = den;
}

__global__ void k_gcf(const float* __restrict__ pnum, const float* __restrict__ pden,
                      const float* __restrict__ ig, const float* __restrict__ og,
                      float* __restrict__ gc, float* __restrict__ gh)
{
    int b = blockIdx.x, h = threadIdx.x;
    float num = 0.f, den = 0.f;
    #pragma unroll
    for (int c = 0; c < NCH; c++) {
        num += pnum[(b * NCH + c) * Hh + h];
        den += pden[(b * NCH + c) * Hh + h];
    }
    float ei = expf(ig[b * Hh + h]);
    float g = (gc[b * Hh + h] * ei + num) / (ei + den);
    gc[b * Hh + h] = g;
    gh[b * Hh + h] = og[b * Hh + h] * tanhf(g);
}

// build fp16 ctx = [h_l, h, h_r] from fp16 hidden
__global__ void k_ctx_bf(const __half* __restrict__ hf, __half* __restrict__ cf)
{
    int i = blockIdx.x * blockDim.x + threadIdx.x;  // 8-elem chunk
    if (i >= BSR * (H3 / 8)) return;
    int bs = i / (H3 / 8);
    int j = (i % (H3 / 8)) * 8;
    int s = bs & (Ss - 1);
    uint4 vh = make_uint4(0, 0, 0, 0);
    long off = -1;
    if (j < Hh)           { if (s > 0)      off = ((long)bs - 1) * Hh + j; }
    else if (j < 2 * Hh)  {                 off = (long)bs * Hh + (j - Hh); }
    else                  { if (s < Ss - 1) off = ((long)bs + 1) * Hh + (j - 2 * Hh); }
    if (off >= 0) vh = *(const uint4*)(hf + off);
    *(uint4*)(cf + (size_t)bs * H3 + j) = vh;
}

// one-pass LN for all 7 groups; z already contains proj
__global__ __launch_bounds__(256) void k_update(
    const float* __restrict__ z,
    const float* __restrict__ gWg, const float* __restrict__ gc,
    const float* __restrict__ mask,
    const float* __restrict__ lns, const float* __restrict__ lnb,
    const float* __restrict__ c_old,
    float* __restrict__ h_new, float* __restrict__ c_new,
    __half* __restrict__ hf)
{
    __shared__ float wsum[8][14];
    __shared__ float fin[14];
    int bs = blockIdx.x; int b = bs >> 10; int s = bs & (Ss - 1);
    int h = threadIdx.x;
    int w = h >> 5, lane = h & 31;
    size_t rz = (size_t)bs * H7;
    float v[7];
    #pragma unroll
    for (int k = 0; k < 7; k++)
        v[k] = z[rz + k * Hh + h] + gWg[b * H7 + k * Hh + h];

    float p[14];
    #pragma unroll
    for (int k = 0; k < 7; k++) { p[2 * k] = v[k]; p[2 * k + 1] = v[k] * v[k]; }
    #pragma unroll
    for (int o = 16; o > 0; o >>= 1)
        #pragma unroll
        for (int j = 0; j < 14; j++)
            p[j] += __shfl_down_sync(0xffffffffu, p[j], o);
    if (lane == 0)
        #pragma unroll
        for (int j = 0; j < 14; j++) wsum[w][j] = p[j];
    __syncthreads();
    if (h < 14) {
        float a = 0.f;
        #pragma unroll
        for (int i = 0; i < 8; i++) a += wsum[i][h];
        fin[h] = a;
    }
    __syncthreads();

    float zn[7];
    #pragma unroll
    for (int k = 0; k < 7; k++) {
        float m = fin[2 * k] * (1.f / 256.f);
        float var = (fin[2 * k + 1] - 256.f * m * m) * (1.f / 255.f);
        zn[k] = lns[(3 + k) * Hh + h] * (v[k] - m) * rsqrtf(var + 1e-6f) + lnb[(3 + k) * Hh + h];
    }
    float e[6], den = 0.f;
    #pragma unroll
    for (int k = 0; k < 6; k++) {
        e[k] = expf(sigmoidf_(zn[k]));
        den += e[k];
    }
    float inv = 1.f / den;
    float mem = tanhf(zn[6]);
    size_t idx = (size_t)bs * Hh + h;
    float c  = c_old[idx];
    float cl = (s > 0)      ? c_old[idx - Hh] : 0.f;
    float cr = (s < Ss - 1) ? c_old[idx + Hh] : 0.f;
    float cn = (e[1] * cl + e[2] * cr + e[3] * c + e[0] * mem + e[4] * gc[b * Hh + h]) * inv;
    float mk = mask[bs];
    float hv = e[5] * inv * tanhf(cn) * mk;
    h_new[idx] = hv;
    c_new[idx] = cn * mk;
    hf[idx] = __float2half(hv);
}

// ---------------- orchestration ----------------------------------------------
extern "C" void kernel_launch(void* const* d_in, const int* in_sizes, int n_in,
                              void* d_out, int out_size)
{
    (void)in_sizes; (void)n_in; (void)out_size;
    const float* inputs = (const float*)d_in[0];
    const float* mask   = (const float*)d_in[1];
    const float* ih     = (const float*)d_in[2];
    const float* ic     = (const float*)d_in[3];
    const float* Wc     = (const float*)d_in[4];
    const float* Wh     = (const float*)d_in[5];
    const float* Wi     = (const float*)d_in[6];
    const float* bi     = (const float*)d_in[7];
    const float* Wg     = (const float*)d_in[8];
    const float* Gi     = (const float*)d_in[9];
    const float* gb     = (const float*)d_in[10];
    const float* Gh     = (const float*)d_in[11];
    const float* Ga     = (const float*)d_in[12];
    const float* lns    = (const float*)d_in[13];
    const float* lnb    = (const float*)d_in[14];
    float* out = (float*)d_out;

    float *hb0, *hb1, *cb0, *cb1, *proj, *zb, *ph;
    float *pi, *pa, *ig, *og, *gh, *gc, *havg, *gWg, *pnum, *pden, *invms;
    __half *ctxf, *hf0, *hf1, *inf;
    __half *w3, *ght, *wit;
    cudaGetSymbolAddress((void**)&hb0,  d_hbuf0);
    cudaGetSymbolAddress((void**)&hb1,  d_hbuf1);
    cudaGetSymbolAddress((void**)&cb0,  d_cbuf0);
    cudaGetSymbolAddress((void**)&cb1,  d_cbuf1);
    cudaGetSymbolAddress((void**)&proj, d_proj);
    cudaGetSymbolAddress((void**)&zb,   d_zbuf);
    cudaGetSymbolAddress((void**)&ph,   d_ph);
    cudaGetSymbolAddress((void**)&pi,   d_pi);
    cudaGetSymbolAddress((void**)&pa,   d_pa);
    cudaGetSymbolAddress((void**)&ig,   d_igb);
    cudaGetSymbolAddress((void**)&og,   d_ogb);
    cudaGetSymbolAddress((void**)&gh,   d_gh);
    cudaGetSymbolAddress((void**)&gc,   d_gcv);
    cudaGetSymbolAddress((void**)&havg, d_havg);
    cudaGetSymbolAddress((void**)&gWg,  d_gWg);
    cudaGetSymbolAddress((void**)&pnum, d_pnum);
    cudaGetSymbolAddress((void**)&pden, d_pden);
    cudaGetSymbolAddress((void**)&invms, d_invms);
    cudaGetSymbolAddress((void**)&ctxf, d_ctx_h);
    cudaGetSymbolAddress((void**)&hf0,  d_h_f0);
    cudaGetSymbolAddress((void**)&hf1,  d_h_f1);
    cudaGetSymbolAddress((void**)&inf,  d_in_f);
    cudaGetSymbolAddress((void**)&w3,   d_W3T);
    cudaGetSymbolAddress((void**)&ght,  d_GhT);
    cudaGetSymbolAddress((void**)&wit,  d_WiT);

    cudaFuncSetAttribute(k_hmma, cudaFuncAttributeMaxDynamicSharedMemorySize, HSMEM);

    static cudaStream_t s2 = [] {
        cudaStream_t s; cudaStreamCreateWithFlags(&s, cudaStreamNonBlocking); return s;
    }();
    static cudaStream_t s3 = [] {
        cudaStream_t s; cudaStreamCreateWithFlags(&s, cudaStreamNonBlocking); return s;
    }();
    static cudaEvent_t evFork = [] {
        cudaEvent_t e; cudaEventCreateWithFlags(&e, cudaEventDisableTiming); return e;
    }();
    static cudaEvent_t evJoin = [] {
        cudaEvent_t e; cudaEventCreateWithFlags(&e, cudaEventDisableTiming); return e;
    }();
    static cudaEvent_t evPh = [] {
        cudaEvent_t e; cudaEventCreateWithFlags(&e, cudaEventDisableTiming); return e;
    }();

    // layer-invariant precompute (main stream)
    k_invms<<<Bb, 256>>>(mask, invms);
    k_meanp<<<dim3(NCH, Bb), 256>>>(ih, mask, pnum);
    k_meanf<<<Bb, 256>>>(pnum, invms, gh);
    k_meanp<<<dim3(NCH, Bb), 256>>>(ic, mask, pnum);
    k_meanf<<<Bb, 256>>>(pnum, invms, gc);
    k_w3t<<<(H7 * H3 + 255) / 256, 256>>>(Wc, Wh, w3);
    k_wt<<<(Hh * Hh + 255) / 256, 256>>>(Gh, Hh, Hh, ght);
    k_wt<<<(H7 * Hh + 255) / 256, 256>>>(Wi, Hh, H7, wit);
    k_cast<<<(BSR * Hh + 255) / 256, 256>>>(ih, hf0, BSR * Hh);
    k_cast<<<(BSR * Hh + 255) / 256, 256>>>(inputs, inf, BSR * Hh);
    k_hmma<<<dim3(H7 / 128, BSR / 128), 256, HSMEM>>>(
        BSR, H7, Hh, inf, wit, bi, (const float*)nullptr, proj);

    float* hbufs[2] = { hb0, hb1 };
    float* cbufs[2] = { cb0, cb1 };
    __half* hfs[2] = { hf0, hf1 };

    for (int l = 0; l < LL; l++) {
        const float* hid = (l == 0) ? ih : hbufs[l & 1];
        const float* cel = (l == 0) ? ic : cbufs[l & 1];
        const __half* hf = hfs[l & 1];
        float* hout = (l == LL - 1) ? out : hbufs[(l + 1) & 1];
        float* cout = cbufs[(l + 1) & 1];

        // fork: both GEMM branches depend only on hidden from prev update
        cudaEventRecord(evFork, 0);
        // s2: z-branch (ctx + z-GEMM, proj fused into epilogue)
        cudaStreamWaitEvent(s2, evFork, 0);
        k_ctx_bf<<<(BSR * (H3 / 8) + 255) / 256, 256, 0, s2>>>(hf, ctxf);
        k_hmma<<<dim3(H7 / 128, BSR / 128), 256, HSMEM, s2>>>(
            BSR, H7, H3, ctxf, w3, (const float*)nullptr, proj, zb);
        cudaEventRecord(evJoin, s2);
        // s3: ph-branch (hidden @ Gh)
        cudaStreamWaitEvent(s3, evFork, 0);
        k_hmma<<<dim3(Hh / 128, BSR / 128), 256, HSMEM, s3>>>(
            BSR, Hh, Hh, hf, ght,
            (const float*)nullptr, (const float*)nullptr, ph);
        cudaEventRecord(evPh, s3);

        // ---- global state chain (main stream, concurrent with both) ----
        k_meanp<<<dim3(NCH, Bb), 256>>>(hid, mask, pnum);
        k_meanf<<<Bb, 256>>>(pnum, invms, havg);
        k_smallgemm<<<(Bb * H3 + 255) / 256, 256>>>(Bb, H3, Hh, gh, Gi, gb, pi);
        k_smallgemm<<<(Bb * 2 * Hh + 255) / 256, 256>>>(Bb, 2 * Hh, Hh, havg, Ga,
                                                        (const float*)nullptr, pa);
        k_igog<<<Bb, 256>>>(pi, pa, lns, lnb, ig, og);
        cudaStreamWaitEvent(0, evPh, 0);
        k_hgcp<<<dim3(NCH, Bb), 256>>>(ph, pi, mask, lns, lnb, cel, pnum, pden);
        k_gcf<<<Bb, 256>>>(pnum, pden, ig, og, gc, gh);
        k_smallgemm<<<(Bb * H7 + 255) / 256, 256>>>(Bb, H7, Hh, gh, Wg,
                                                    (const float*)nullptr, gWg);

        // join: update needs z (s2) + gWg/gc (main)
        cudaStreamWaitEvent(0, evJoin, 0);
        k_update<<<BSR, 256>>>(zb, gWg, gc, mask, lns, lnb, cel, hout, cout,
                               hfs[(l + 1) & 1]);
    }
}